// round 1
// baseline (speedup 1.0000x reference)
#include <cuda_runtime.h>
#include <math.h>

#define NODES_MAX 100000
#define EDGES_MAX 1600000
#define G_MAX     2048
#define SCAN_B    512

// ---------------- scratch (device globals; no allocation allowed) -------------
__device__ int    g_degi[NODES_MAX];
__device__ float  g_dinv[NODES_MAX];
__device__ int    g_rowstart[NODES_MAX + 1];
__device__ int    g_cursor[NODES_MAX];
__device__ int    g_bsum[SCAN_B];
__device__ int    g_boff[SCAN_B];
__device__ int    g_csr[EDGES_MAX];
__device__ float4 g_xws[NODES_MAX * 16];     // dinv[i] * (feat @ W)  (64 f = 16 float4)
__device__ float4 g_h1[NODES_MAX * 16];      // layer-1 activations
__device__ float4 g_pooled[G_MAX * 16];
__device__ float  g_cnt[G_MAX];

// ---------------- small helpers ----------------------------------------------
__device__ __forceinline__ float4 f4zero() { return make_float4(0.f, 0.f, 0.f, 0.f); }
__device__ __forceinline__ void f4add(float4& a, const float4 b) {
    a.x += b.x; a.y += b.y; a.z += b.z; a.w += b.w;
}
__device__ __forceinline__ void f4fma(float4& a, float s, const float4 b) {
    a.x = fmaf(s, b.x, a.x); a.y = fmaf(s, b.y, a.y);
    a.z = fmaf(s, b.z, a.z); a.w = fmaf(s, b.w, a.w);
}

// ---------------- kernels -----------------------------------------------------

__global__ void k_zero(int N, int G) {
    int i = blockIdx.x * blockDim.x + threadIdx.x;
    if (i < N) g_degi[i] = 0;
    if (i < G * 16) g_pooled[i] = f4zero();
    if (i < G) g_cnt[i] = 0.f;
}

__global__ void k_deg(const int* __restrict__ dst, int E) {
    int e = blockIdx.x * blockDim.x + threadIdx.x;
    if (e < E) atomicAdd(&g_degi[dst[e]], 1);
}

__global__ void k_dinv(int N) {
    int i = blockIdx.x * blockDim.x + threadIdx.x;
    if (i < N) g_dinv[i] = rsqrtf((float)(g_degi[i] + 1));  // +1 self loop, deg>=1
}

// exclusive scan of degrees, 3-phase
__global__ void k_scan1(int N) {
    __shared__ int sh[SCAN_B];
    int t = threadIdx.x;
    int gid = blockIdx.x * SCAN_B + t;
    int v = (gid < N) ? g_degi[gid] : 0;
    sh[t] = v;
    __syncthreads();
#pragma unroll
    for (int off = 1; off < SCAN_B; off <<= 1) {
        int a = (t >= off) ? sh[t - off] : 0;
        __syncthreads();
        sh[t] += a;
        __syncthreads();
    }
    if (gid < N) g_rowstart[gid] = sh[t] - v;      // local exclusive
    if (t == SCAN_B - 1) g_bsum[blockIdx.x] = sh[t];
}

__global__ void k_scan2(int nb) {
    __shared__ int sh[SCAN_B];
    int t = threadIdx.x;
    int v = (t < nb) ? g_bsum[t] : 0;
    sh[t] = v;
    __syncthreads();
#pragma unroll
    for (int off = 1; off < SCAN_B; off <<= 1) {
        int a = (t >= off) ? sh[t - off] : 0;
        __syncthreads();
        sh[t] += a;
        __syncthreads();
    }
    g_boff[t] = sh[t] - v;                          // exclusive block offsets
}

__global__ void k_scan3(int N, int E) {
    int i = blockIdx.x * blockDim.x + threadIdx.x;
    if (i < N) {
        int r = g_rowstart[i] + g_boff[i >> 9];     // SCAN_B == 512
        g_rowstart[i] = r;
        g_cursor[i] = r;
    }
    if (i == 0) g_rowstart[N] = E;
}

__global__ void k_fill(const int* __restrict__ src, const int* __restrict__ dst, int E) {
    int e = blockIdx.x * blockDim.x + threadIdx.x;
    if (e < E) {
        int d = dst[e];
        int p = atomicAdd(&g_cursor[d], 1);
        g_csr[p] = src[e];
    }
}

// xws1[i] = dinv[i] * (x[i] @ W1);  thread per node, 64 outputs in regs.
__global__ void k_xws1(int N, const float* __restrict__ x, const float* __restrict__ W1) {
    int i = blockIdx.x * blockDim.x + threadIdx.x;
    if (i >= N) return;
    float xr[6];
#pragma unroll
    for (int k = 0; k < 6; k++) xr[k] = __ldg(&x[i * 6 + k]);
    const float4* W14 = (const float4*)W1;          // [6][16] float4
    float4 acc[16];
#pragma unroll
    for (int c = 0; c < 16; c++) acc[c] = f4zero();
#pragma unroll
    for (int k = 0; k < 6; k++) {
#pragma unroll
        for (int c = 0; c < 16; c++) {
            float4 w = __ldg(&W14[k * 16 + c]);
            f4fma(acc[c], xr[k], w);
        }
    }
    float di = g_dinv[i];
#pragma unroll
    for (int c = 0; c < 16; c++) {
        float4 o; o.x = di * acc[c].x; o.y = di * acc[c].y;
        o.z = di * acc[c].z; o.w = di * acc[c].w;
        g_xws[i * 16 + c] = o;
    }
}

// xws2[i] = dinv[i] * (h1[i] @ W2); thread per node, chunked over K.
__global__ void k_xws2(int N, const float* __restrict__ W2) {
    int i = blockIdx.x * blockDim.x + threadIdx.x;
    if (i >= N) return;
    const float4* W24 = (const float4*)W2;          // [64][16] float4
    const float4* hrow = &g_h1[i * 16];
    float4 acc[16];
#pragma unroll
    for (int c = 0; c < 16; c++) acc[c] = f4zero();
    for (int kc = 0; kc < 16; kc++) {               // rolled: 16 iters x 4 k-steps
        float4 h4 = hrow[kc];
        float hk[4] = {h4.x, h4.y, h4.z, h4.w};
#pragma unroll
        for (int kk = 0; kk < 4; kk++) {
            int k = kc * 4 + kk;
            float hv = hk[kk];
#pragma unroll
            for (int c = 0; c < 16; c++) {
                float4 w = __ldg(&W24[k * 16 + c]);
                f4fma(acc[c], hv, w);
            }
        }
    }
    float di = g_dinv[i];
#pragma unroll
    for (int c = 0; c < 16; c++) {
        float4 o; o.x = di * acc[c].x; o.y = di * acc[c].y;
        o.z = di * acc[c].z; o.w = di * acc[c].w;
        g_xws[i * 16 + c] = o;
    }
}

// Aggregation: 16 lanes per node, one float4 column each.
// MODE 0: h1[i] = relu(dinv[i]*(sum + self) + b)  (stores to g_h1)
// MODE 1: h2 computed the same way, directly pooled per-graph (atomics).
template <int MODE>
__global__ void k_agg(int N, const float* __restrict__ bias, const int* __restrict__ batch) {
    int t = blockIdx.x * blockDim.x + threadIdx.x;
    int i = t >> 4;
    int c = t & 15;
    if (i >= N) return;
    float4 acc = g_xws[i * 16 + c];                 // self loop contribution
    int beg = g_rowstart[i];
    int end = g_rowstart[i + 1];
    for (int j = beg; j < end; j++) {
        int s = g_csr[j];
        float4 v = g_xws[s * 16 + c];
        f4add(acc, v);
    }
    float di = g_dinv[i];
    float4 b = __ldg(&((const float4*)bias)[c]);
    float4 h;
    h.x = fmaxf(fmaf(di, acc.x, b.x), 0.f);
    h.y = fmaxf(fmaf(di, acc.y, b.y), 0.f);
    h.z = fmaxf(fmaf(di, acc.z, b.z), 0.f);
    h.w = fmaxf(fmaf(di, acc.w, b.w), 0.f);
    if (MODE == 0) {
        g_h1[i * 16 + c] = h;
    } else {
        int g = batch[i];
        float* p = (float*)&g_pooled[g * 16 + c];
        atomicAdd(p + 0, h.x);
        atomicAdd(p + 1, h.y);
        atomicAdd(p + 2, h.z);
        atomicAdd(p + 3, h.w);
        if (c == 0) atomicAdd(&g_cnt[g], 1.f);
    }
}

// Final MLP: 2 graphs per 128-thread block, 64 threads per graph.
__global__ void k_mlp(int G,
                      const float* __restrict__ embL, const float* __restrict__ embA,
                      const float* __restrict__ embB, const float* __restrict__ embAr,
                      const int* __restrict__ lig, const int* __restrict__ add,
                      const int* __restrict__ base, const int* __restrict__ aryl,
                      const float* __restrict__ lin1W, const float* __restrict__ lin1b,
                      const float* __restrict__ lin2W, const float* __restrict__ lin2b,
                      float* __restrict__ out) {
    __shared__ float cat[2][128];
    __shared__ float red[2][2];
    int local = threadIdx.x >> 6;
    int o = threadIdx.x & 63;
    int g = blockIdx.x * 2 + local;
    if (g < G) {
        float cnt = fmaxf(g_cnt[g], 1.f);
        const float* pooled = (const float*)&g_pooled[g * 16];
        cat[local][o] = pooled[o] / cnt;
        float ev;
        if (o < 16)       ev = embL[lig[g] * 16 + o];
        else if (o < 32)  ev = embA[add[g] * 16 + (o - 16)];
        else if (o < 48)  ev = embB[base[g] * 16 + (o - 32)];
        else              ev = embAr[aryl[g] * 16 + (o - 48)];
        cat[local][64 + o] = ev;
    }
    __syncthreads();
    float term = 0.f;
    if (g < G) {
        float acc = lin1b[o];
#pragma unroll 8
        for (int k = 0; k < 128; k++)
            acc = fmaf(cat[local][k], __ldg(&lin1W[k * 64 + o]), acc);
        acc = fmaxf(acc, 0.f);
        term = acc * __ldg(&lin2W[o]);
#pragma unroll
        for (int off = 16; off > 0; off >>= 1)
            term += __shfl_down_sync(0xffffffffu, term, off);
        if ((o & 31) == 0) red[local][o >> 5] = term;
    }
    __syncthreads();
    if (g < G && o == 0) out[g] = red[local][0] + red[local][1] + lin2b[0];
}

// ---------------- launch ------------------------------------------------------
extern "C" void kernel_launch(void* const* d_in, const int* in_sizes, int n_in,
                              void* d_out, int out_size) {
    const float* x      = (const float*)d_in[0];
    const int*   ei     = (const int*)d_in[1];
    const int*   batch  = (const int*)d_in[2];
    const int*   lig    = (const int*)d_in[3];
    const int*   addi   = (const int*)d_in[4];
    const int*   basei  = (const int*)d_in[5];
    const int*   aryl   = (const int*)d_in[6];
    const float* embL   = (const float*)d_in[7];
    const float* embA   = (const float*)d_in[8];
    const float* embB   = (const float*)d_in[9];
    const float* embAr  = (const float*)d_in[10];
    const float* W1     = (const float*)d_in[11];
    const float* b1     = (const float*)d_in[12];
    const float* W2     = (const float*)d_in[13];
    const float* b2     = (const float*)d_in[14];
    const float* lin1W  = (const float*)d_in[15];
    const float* lin1b  = (const float*)d_in[16];
    const float* lin2W  = (const float*)d_in[17];
    const float* lin2b  = (const float*)d_in[18];

    int N = in_sizes[0] / 6;
    int E = in_sizes[1] / 2;
    int G = in_sizes[3];
    const int* src = ei;
    const int* dst = ei + E;
    int nb = (N + SCAN_B - 1) / SCAN_B;

    int zmax = N > G * 16 ? N : G * 16;
    k_zero<<<(zmax + 255) / 256, 256>>>(N, G);
    k_deg<<<(E + 255) / 256, 256>>>(dst, E);
    k_dinv<<<(N + 255) / 256, 256>>>(N);
    k_scan1<<<nb, SCAN_B>>>(N);
    k_scan2<<<1, SCAN_B>>>(nb);
    k_scan3<<<(N + 255) / 256, 256>>>(N, E);
    k_fill<<<(E + 255) / 256, 256>>>(src, dst, E);

    k_xws1<<<(N + 127) / 128, 128>>>(N, x, W1);
    k_agg<0><<<((long)N * 16 + 255) / 256, 256>>>(N, b1, nullptr);
    k_xws2<<<(N + 127) / 128, 128>>>(N, W2);
    k_agg<1><<<((long)N * 16 + 255) / 256, 256>>>(N, b2, batch);

    k_mlp<<<(G + 1) / 2, 128>>>(G, embL, embA, embB, embAr,
                                lig, addi, basei, aryl,
                                lin1W, lin1b, lin2W, lin2b, (float*)d_out);
}

// round 2
// speedup vs baseline: 1.0325x; 1.0325x over previous
#include <cuda_runtime.h>
#include <cuda_fp16.h>
#include <math.h>

#define NODES_MAX 100000
#define EDGES_MAX 1600000
#define G_MAX     2048
#define SCAN_B    512

// ---------------- scratch (device globals; no allocation allowed) -------------
__device__ int    g_degi[NODES_MAX];
__device__ float  g_dinv[NODES_MAX];
__device__ int    g_rowstart[NODES_MAX + 1];
__device__ int    g_cursor[NODES_MAX];
__device__ int    g_bsum[SCAN_B];
__device__ int    g_boff[SCAN_B];
__device__ int    g_csr[EDGES_MAX];
__device__ float4 g_xs[NODES_MAX * 2];        // dinv[i]*x[i], padded to 8 floats
__device__ __half g_hs[NODES_MAX * 64];       // dinv[i]*h1[i] in half (128B/row)
__device__ float  g_t[NODES_MAX * 64];        // layer-2 aggregated (pre-W2)
__device__ float4 g_pooled[G_MAX * 16];
__device__ float  g_cnt[G_MAX];

// ---------------- helpers ------------------------------------------------------
__device__ __forceinline__ float4 f4zero() { return make_float4(0.f, 0.f, 0.f, 0.f); }
__device__ __forceinline__ void f4add(float4& a, const float4 b) {
    a.x += b.x; a.y += b.y; a.z += b.z; a.w += b.w;
}
__device__ __forceinline__ void f4fma(float4& a, float s, const float4 b) {
    a.x = fmaf(s, b.x, a.x); a.y = fmaf(s, b.y, a.y);
    a.z = fmaf(s, b.z, a.z); a.w = fmaf(s, b.w, a.w);
}

// ---------------- CSR build ----------------------------------------------------

__global__ void k_zero(int N, int G) {
    int i = blockIdx.x * blockDim.x + threadIdx.x;
    if (i < N) g_degi[i] = 0;
    if (i < G * 16) g_pooled[i] = f4zero();
    if (i < G) g_cnt[i] = 0.f;
}

__global__ void k_deg(const int* __restrict__ dst, int E) {
    int e = blockIdx.x * blockDim.x + threadIdx.x;
    if (e < E) atomicAdd(&g_degi[dst[e]], 1);
}

// warp-shuffle exclusive scan of degrees; also computes dinv.
__global__ void k_scan1(int N) {
    __shared__ int wsum[16];
    int t = threadIdx.x, lane = t & 31, w = t >> 5;
    int gid = blockIdx.x * SCAN_B + t;
    int deg = (gid < N) ? g_degi[gid] : 0;
    if (gid < N) g_dinv[gid] = rsqrtf((float)(deg + 1));
    int v = deg;
#pragma unroll
    for (int off = 1; off < 32; off <<= 1) {
        int n = __shfl_up_sync(0xffffffffu, v, off);
        if (lane >= off) v += n;
    }
    if (lane == 31) wsum[w] = v;
    __syncthreads();
    if (w == 0) {
        int s = (lane < 16) ? wsum[lane] : 0;
#pragma unroll
        for (int off = 1; off < 16; off <<= 1) {
            int n = __shfl_up_sync(0xffffffffu, s, off);
            if (lane >= off) s += n;
        }
        if (lane < 16) wsum[lane] = s;
    }
    __syncthreads();
    int base = (w > 0) ? wsum[w - 1] : 0;
    int incl = v + base;
    if (gid < N) g_rowstart[gid] = incl - deg;   // local exclusive
    if (t == SCAN_B - 1) g_bsum[blockIdx.x] = incl;
}

__global__ void k_scan2(int nb) {
    __shared__ int wsum[16];
    int t = threadIdx.x, lane = t & 31, w = t >> 5;
    int val = (t < nb) ? g_bsum[t] : 0;
    int v = val;
#pragma unroll
    for (int off = 1; off < 32; off <<= 1) {
        int n = __shfl_up_sync(0xffffffffu, v, off);
        if (lane >= off) v += n;
    }
    if (lane == 31) wsum[w] = v;
    __syncthreads();
    if (w == 0) {
        int s = (lane < 16) ? wsum[lane] : 0;
#pragma unroll
        for (int off = 1; off < 16; off <<= 1) {
            int n = __shfl_up_sync(0xffffffffu, s, off);
            if (lane >= off) s += n;
        }
        if (lane < 16) wsum[lane] = s;
    }
    __syncthreads();
    int base = (w > 0) ? wsum[w - 1] : 0;
    g_boff[t] = v + base - val;                 // exclusive block offsets
}

__global__ void k_scan3(int N, int E) {
    int i = blockIdx.x * blockDim.x + threadIdx.x;
    if (i < N) {
        int r = g_rowstart[i] + g_boff[i >> 9];  // SCAN_B == 512
        g_rowstart[i] = r;
        g_cursor[i] = r;
    }
    if (i == 0) g_rowstart[N] = E;
}

__global__ void k_fill(const int* __restrict__ src, const int* __restrict__ dst, int E) {
    int e = blockIdx.x * blockDim.x + threadIdx.x;
    if (e < E) {
        int d = dst[e];
        int p = atomicAdd(&g_cursor[d], 1);
        g_csr[p] = src[e];
    }
}

// ---------------- layer 1 ------------------------------------------------------

// xs[i] = dinv[i]*x[i], padded to 8 floats (2 float4 per node).
__global__ void k_pre1(int N, const float* __restrict__ x) {
    int i = blockIdx.x * blockDim.x + threadIdx.x;
    if (i >= N) return;
    float d = g_dinv[i];
    const float* xr = x + i * 6;
    float4 a, b;
    a.x = d * xr[0]; a.y = d * xr[1]; a.z = d * xr[2]; a.w = d * xr[3];
    b.x = d * xr[4]; b.y = d * xr[5]; b.z = 0.f; b.w = 0.f;
    g_xs[i * 2 + 0] = a;
    g_xs[i * 2 + 1] = b;
}

// Fused layer 1: aggregate xs (6-dim) -> @W1 + b1 -> relu -> *dinv -> store half hs.
// 2 lanes per node; each lane handles one float4 of the padded input and 32 outputs.
__global__ void k_layer1(int N, const float* __restrict__ W1, const float* __restrict__ b1) {
    int t = blockIdx.x * blockDim.x + threadIdx.x;
    int i = t >> 1;
    int hf = t & 1;
    if (i >= N) return;
    float4 acc = g_xs[i * 2 + hf];                  // self-loop term
    int beg = g_rowstart[i], end = g_rowstart[i + 1];
    for (int j = beg; j < end; j++) {
        int s = g_csr[j];
        f4add(acc, g_xs[s * 2 + hf]);
    }
    // exchange within lane pair: assemble a[0..5]
    float4 other;
    other.x = __shfl_xor_sync(0xffffffffu, acc.x, 1);
    other.y = __shfl_xor_sync(0xffffffffu, acc.y, 1);
    other.z = __shfl_xor_sync(0xffffffffu, acc.z, 1);
    other.w = __shfl_xor_sync(0xffffffffu, acc.w, 1);
    float a[6];
    if (hf == 0) { a[0]=acc.x; a[1]=acc.y; a[2]=acc.z; a[3]=acc.w; a[4]=other.x; a[5]=other.y; }
    else         { a[0]=other.x; a[1]=other.y; a[2]=other.z; a[3]=other.w; a[4]=acc.x; a[5]=acc.y; }

    const float4* W14 = (const float4*)W1;          // [6][16] float4
    const float4* b14 = (const float4*)b1;          // [16] float4
    float4 out[8];
#pragma unroll
    for (int c = 0; c < 8; c++) out[c] = f4zero();
#pragma unroll
    for (int k = 0; k < 6; k++) {
#pragma unroll
        for (int c = 0; c < 8; c++) {
            float4 w = __ldg(&W14[k * 16 + hf * 8 + c]);
            f4fma(out[c], a[k], w);
        }
    }
    float di = g_dinv[i];
    __half2 hh[16];
#pragma unroll
    for (int c = 0; c < 8; c++) {
        float4 b = __ldg(&b14[hf * 8 + c]);
        float hx = fmaxf(fmaf(di, out[c].x, b.x), 0.f) * di;
        float hy = fmaxf(fmaf(di, out[c].y, b.y), 0.f) * di;
        float hz = fmaxf(fmaf(di, out[c].z, b.z), 0.f) * di;
        float hw = fmaxf(fmaf(di, out[c].w, b.w), 0.f) * di;
        hh[2 * c + 0] = __floats2half2_rn(hx, hy);
        hh[2 * c + 1] = __floats2half2_rn(hz, hw);
    }
    uint4* dst = (uint4*)(g_hs + (size_t)i * 64 + hf * 32);
    const uint4* s4 = (const uint4*)hh;
#pragma unroll
    for (int q = 0; q < 4; q++) dst[q] = s4[q];
}

// ---------------- layer 2 ------------------------------------------------------

// Aggregate hs (half, 128B/row) into g_t (fp32). 8 lanes per node, 8 halves each.
__global__ void k_agg2(int N) {
    int t = blockIdx.x * blockDim.x + threadIdx.x;
    int i = t >> 3;
    int c = t & 7;
    if (i >= N) return;
    const uint4* hs4 = (const uint4*)g_hs;          // 8 halves per uint4; 8 per row
    float acc[8];
    {
        uint4 v = hs4[(size_t)i * 8 + c];           // self
        const __half2* ph = (const __half2*)&v;
#pragma unroll
        for (int j = 0; j < 4; j++) {
            float2 f = __half22float2(ph[j]);
            acc[2 * j] = f.x; acc[2 * j + 1] = f.y;
        }
    }
    int beg = g_rowstart[i], end = g_rowstart[i + 1];
    for (int j = beg; j < end; j++) {
        int s = g_csr[j];
        uint4 v = hs4[(size_t)s * 8 + c];
        const __half2* ph = (const __half2*)&v;
#pragma unroll
        for (int q = 0; q < 4; q++) {
            float2 f = __half22float2(ph[q]);
            acc[2 * q] += f.x; acc[2 * q + 1] += f.y;
        }
    }
    float4* tp = (float4*)(g_t + (size_t)i * 64 + c * 8);
    tp[0] = make_float4(acc[0], acc[1], acc[2], acc[3]);
    tp[1] = make_float4(acc[4], acc[5], acc[6], acc[7]);
}

// Fused: t*dinv @ W2 + b2 -> relu -> pooled atomics. Thread per node; W2 warp-uniform.
__global__ void __launch_bounds__(128) k_post2(int N, const float* __restrict__ W2,
                                               const float* __restrict__ b2,
                                               const int* __restrict__ batch) {
    int i = blockIdx.x * blockDim.x + threadIdx.x;
    if (i >= N) return;
    const float4* W24 = (const float4*)W2;          // [64][16] float4
    const float4* trow = (const float4*)(g_t + (size_t)i * 64);
    float4 acc[16];
#pragma unroll
    for (int c = 0; c < 16; c++) acc[c] = f4zero();
    for (int kc = 0; kc < 16; kc++) {
        float4 h4 = trow[kc];
        float hk[4] = {h4.x, h4.y, h4.z, h4.w};
#pragma unroll
        for (int kk = 0; kk < 4; kk++) {
            int k = kc * 4 + kk;
            float hv = hk[kk];
#pragma unroll
            for (int c = 0; c < 16; c++) {
                float4 w = __ldg(&W24[k * 16 + c]);
                f4fma(acc[c], hv, w);
            }
        }
    }
    float di = g_dinv[i];
    int g = batch[i];
    float* pp = (float*)&g_pooled[g * 16];
    const float4* b24 = (const float4*)b2;
#pragma unroll
    for (int c = 0; c < 16; c++) {
        float4 b = __ldg(&b24[c]);
        float hx = fmaxf(fmaf(di, acc[c].x, b.x), 0.f);
        float hy = fmaxf(fmaf(di, acc[c].y, b.y), 0.f);
        float hz = fmaxf(fmaf(di, acc[c].z, b.z), 0.f);
        float hw = fmaxf(fmaf(di, acc[c].w, b.w), 0.f);
        atomicAdd(pp + 4 * c + 0, hx);
        atomicAdd(pp + 4 * c + 1, hy);
        atomicAdd(pp + 4 * c + 2, hz);
        atomicAdd(pp + 4 * c + 3, hw);
    }
    atomicAdd(&g_cnt[g], 1.f);
}

// ---------------- final MLP ----------------------------------------------------
__global__ void k_mlp(int G,
                      const float* __restrict__ embL, const float* __restrict__ embA,
                      const float* __restrict__ embB, const float* __restrict__ embAr,
                      const int* __restrict__ lig, const int* __restrict__ add,
                      const int* __restrict__ base, const int* __restrict__ aryl,
                      const float* __restrict__ lin1W, const float* __restrict__ lin1b,
                      const float* __restrict__ lin2W, const float* __restrict__ lin2b,
                      float* __restrict__ out) {
    __shared__ float cat[2][128];
    __shared__ float red[2][2];
    int local = threadIdx.x >> 6;
    int o = threadIdx.x & 63;
    int g = blockIdx.x * 2 + local;
    if (g < G) {
        float cnt = fmaxf(g_cnt[g], 1.f);
        const float* pooled = (const float*)&g_pooled[g * 16];
        cat[local][o] = pooled[o] / cnt;
        float ev;
        if (o < 16)       ev = embL[lig[g] * 16 + o];
        else if (o < 32)  ev = embA[add[g] * 16 + (o - 16)];
        else if (o < 48)  ev = embB[base[g] * 16 + (o - 32)];
        else              ev = embAr[aryl[g] * 16 + (o - 48)];
        cat[local][64 + o] = ev;
    }
    __syncthreads();
    float term = 0.f;
    if (g < G) {
        float acc = lin1b[o];
#pragma unroll 8
        for (int k = 0; k < 128; k++)
            acc = fmaf(cat[local][k], __ldg(&lin1W[k * 64 + o]), acc);
        acc = fmaxf(acc, 0.f);
        term = acc * __ldg(&lin2W[o]);
#pragma unroll
        for (int off = 16; off > 0; off >>= 1)
            term += __shfl_down_sync(0xffffffffu, term, off);
        if ((o & 31) == 0) red[local][o >> 5] = term;
    }
    __syncthreads();
    if (g < G && o == 0) out[g] = red[local][0] + red[local][1] + lin2b[0];
}

// ---------------- launch ------------------------------------------------------
extern "C" void kernel_launch(void* const* d_in, const int* in_sizes, int n_in,
                              void* d_out, int out_size) {
    const float* x      = (const float*)d_in[0];
    const int*   ei     = (const int*)d_in[1];
    const int*   batch  = (const int*)d_in[2];
    const int*   lig    = (const int*)d_in[3];
    const int*   addi   = (const int*)d_in[4];
    const int*   basei  = (const int*)d_in[5];
    const int*   aryl   = (const int*)d_in[6];
    const float* embL   = (const float*)d_in[7];
    const float* embA   = (const float*)d_in[8];
    const float* embB   = (const float*)d_in[9];
    const float* embAr  = (const float*)d_in[10];
    const float* W1     = (const float*)d_in[11];
    const float* b1     = (const float*)d_in[12];
    const float* W2     = (const float*)d_in[13];
    const float* b2     = (const float*)d_in[14];
    const float* lin1W  = (const float*)d_in[15];
    const float* lin1b  = (const float*)d_in[16];
    const float* lin2W  = (const float*)d_in[17];
    const float* lin2b  = (const float*)d_in[18];

    int N = in_sizes[0] / 6;
    int E = in_sizes[1] / 2;
    int G = in_sizes[3];
    const int* src = ei;
    const int* dst = ei + E;
    int nb = (N + SCAN_B - 1) / SCAN_B;

    int zmax = N > G * 16 ? N : G * 16;
    k_zero<<<(zmax + 255) / 256, 256>>>(N, G);
    k_deg<<<(E + 255) / 256, 256>>>(dst, E);
    k_scan1<<<nb, SCAN_B>>>(N);
    k_scan2<<<1, SCAN_B>>>(nb);
    k_scan3<<<(N + 255) / 256, 256>>>(N, E);
    k_fill<<<(E + 255) / 256, 256>>>(src, dst, E);

    k_pre1<<<(N + 255) / 256, 256>>>(N, x);
    k_layer1<<<((long)N * 2 + 255) / 256, 256>>>(N, W1, b1);
    k_agg2<<<((long)N * 8 + 255) / 256, 256>>>(N);
    k_post2<<<(N + 127) / 128, 128>>>(N, W2, b2, batch);

    k_mlp<<<(G + 1) / 2, 128>>>(G, embL, embA, embB, embAr,
                                lig, addi, basei, aryl,
                                lin1W, lin1b, lin2W, lin2b, (float*)d_out);
}

// round 3
// speedup vs baseline: 1.2787x; 1.2385x over previous
#include <cuda_runtime.h>
#include <cuda_fp16.h>
#include <math.h>

#define NODES_MAX 100000
#define EDGES_MAX 1600000
#define G_MAX     2048
#define SCAN_B    512

typedef unsigned long long ull;

// ---------------- scratch (device globals; no allocation allowed) -------------
__device__ int    g_degi[NODES_MAX];
__device__ float  g_dinv[NODES_MAX];
__device__ int    g_rowstart[NODES_MAX + 1];
__device__ int    g_cursor[NODES_MAX];
__device__ int    g_bflag[SCAN_B];            // decoupled-lookback aggregates (+1)
__device__ int    g_csr[EDGES_MAX];
__device__ float4 g_xs[NODES_MAX * 2];        // dinv[i]*x[i], padded to 8 floats
__device__ __half g_hs[NODES_MAX * 64];       // dinv[i]*h1[i] in half (128B/row)
__device__ ulonglong2 g_W2p[64 * 16];         // W2 packed as f32x2 pairs [64][32]
__device__ float4 g_pooled[G_MAX * 16];
__device__ float  g_cnt[G_MAX];

// ---------------- helpers ------------------------------------------------------
__device__ __forceinline__ float4 f4zero() { return make_float4(0.f, 0.f, 0.f, 0.f); }
__device__ __forceinline__ void f4add(float4& a, const float4 b) {
    a.x += b.x; a.y += b.y; a.z += b.z; a.w += b.w;
}
__device__ __forceinline__ void f4fma(float4& a, float s, const float4 b) {
    a.x = fmaf(s, b.x, a.x); a.y = fmaf(s, b.y, a.y);
    a.z = fmaf(s, b.z, a.z); a.w = fmaf(s, b.w, a.w);
}
__device__ __forceinline__ ull pk2(float lo, float hi) {
    ull r; asm("mov.b64 %0, {%1,%2};" : "=l"(r) : "f"(lo), "f"(hi)); return r;
}
__device__ __forceinline__ float2 upk2(ull v) {
    float2 f; asm("mov.b64 {%0,%1}, %2;" : "=f"(f.x), "=f"(f.y) : "l"(v)); return f;
}
__device__ __forceinline__ ull f2fma(ull a, ull b, ull c) {
    ull d; asm("fma.rn.f32x2 %0, %1, %2, %3;" : "=l"(d) : "l"(a), "l"(b), "l"(c)); return d;
}
__device__ __forceinline__ void addcvt(float* a, uint4 v) {
    const __half2* h = (const __half2*)&v;
#pragma unroll
    for (int p = 0; p < 4; p++) {
        float2 f = __half22float2(h[p]);
        a[2 * p] += f.x; a[2 * p + 1] += f.y;
    }
}

// ---------------- setup: zero scratch + pack W2 --------------------------------
__global__ void k_zero(int N, int G, const float* __restrict__ W2) {
    int i = blockIdx.x * blockDim.x + threadIdx.x;
    if (i < N) g_degi[i] = 0;
    if (i < G * 16) g_pooled[i] = f4zero();
    if (i < G) g_cnt[i] = 0.f;
    if (i < SCAN_B) g_bflag[i] = 0;
    if (i < 64 * 32) {
        int k = i >> 5, p = i & 31;
        ull v = pk2(W2[k * 64 + 2 * p], W2[k * 64 + 2 * p + 1]);
        ((ull*)g_W2p)[(size_t)k * 32 + p] = v;
    }
}

// ---------------- degree count (vectorized) ------------------------------------
__global__ void k_deg(const int* __restrict__ dst, int E) {
    int idx = blockIdx.x * blockDim.x + threadIdx.x;
    int e = idx * 4;
    if (e + 3 < E) {
        int4 d = *(const int4*)(dst + e);
        atomicAdd(&g_degi[d.x], 1);
        atomicAdd(&g_degi[d.y], 1);
        atomicAdd(&g_degi[d.z], 1);
        atomicAdd(&g_degi[d.w], 1);
    } else {
        for (; e < E; e++) atomicAdd(&g_degi[dst[e]], 1);
    }
}

// ---------------- fused scan: rowstart/cursor/dinv/xs in one kernel ------------
// Decoupled lookback: all blocks resident (<=196 blocks, 4/SM capacity 592).
__global__ void __launch_bounds__(SCAN_B) k_scanfuse(int N, int E, const float* __restrict__ x) {
    __shared__ int wsum[16];
    __shared__ int s_prefix;
    int t = threadIdx.x, lane = t & 31, w = t >> 5;
    int gid = blockIdx.x * SCAN_B + t;
    int deg = (gid < N) ? g_degi[gid] : 0;
    int v = deg;
#pragma unroll
    for (int off = 1; off < 32; off <<= 1) {
        int n = __shfl_up_sync(0xffffffffu, v, off);
        if (lane >= off) v += n;
    }
    if (lane == 31) wsum[w] = v;
    __syncthreads();
    if (w == 0) {
        int s = (lane < 16) ? wsum[lane] : 0;
#pragma unroll
        for (int off = 1; off < 16; off <<= 1) {
            int n = __shfl_up_sync(0xffffffffu, s, off);
            if (lane >= off) s += n;
        }
        if (lane < 16) wsum[lane] = s;
    }
    __syncthreads();
    int base = (w > 0) ? wsum[w - 1] : 0;
    int incl = v + base;
    // publish block aggregate (+1 sentinel)
    if (t == SCAN_B - 1) {
        __threadfence();
        atomicExch(&g_bflag[blockIdx.x], incl + 1);
    }
    // sum predecessor aggregates (warp 0)
    if (w == 0) {
        int sum = 0;
        for (int p = lane; p < blockIdx.x; p += 32) {
            int f;
            volatile int* fp = &g_bflag[p];
            do { f = *fp; } while (f == 0);
            sum += f - 1;
        }
#pragma unroll
        for (int off = 16; off > 0; off >>= 1)
            sum += __shfl_down_sync(0xffffffffu, sum, off);
        if (lane == 0) s_prefix = sum;
    }
    __syncthreads();
    if (gid < N) {
        int rs = incl - deg + s_prefix;
        g_rowstart[gid] = rs;
        g_cursor[gid] = rs;
        float d = rsqrtf((float)(deg + 1));
        g_dinv[gid] = d;
        const float* xr = x + (size_t)gid * 6;
        float4 a, b;
        a.x = d * xr[0]; a.y = d * xr[1]; a.z = d * xr[2]; a.w = d * xr[3];
        b.x = d * xr[4]; b.y = d * xr[5]; b.z = 0.f; b.w = 0.f;
        g_xs[gid * 2 + 0] = a;
        g_xs[gid * 2 + 1] = b;
    }
    if (gid == 0) g_rowstart[N] = E;
}

// ---------------- CSR fill (vectorized) ----------------------------------------
__global__ void k_fill(const int* __restrict__ src, const int* __restrict__ dst, int E) {
    int idx = blockIdx.x * blockDim.x + threadIdx.x;
    int e = idx * 4;
    if (e + 3 < E) {
        int4 d = *(const int4*)(dst + e);
        int4 s = *(const int4*)(src + e);
        g_csr[atomicAdd(&g_cursor[d.x], 1)] = s.x;
        g_csr[atomicAdd(&g_cursor[d.y], 1)] = s.y;
        g_csr[atomicAdd(&g_cursor[d.z], 1)] = s.z;
        g_csr[atomicAdd(&g_cursor[d.w], 1)] = s.w;
    } else {
        for (; e < E; e++)
            g_csr[atomicAdd(&g_cursor[dst[e]], 1)] = src[e];
    }
}

// ---------------- layer 1: aggregate(6d) -> @W1 -> relu -> *dinv -> half hs ----
__global__ void k_layer1(int N, const float* __restrict__ W1, const float* __restrict__ b1) {
    int t = blockIdx.x * blockDim.x + threadIdx.x;
    int i = t >> 1;
    int hf = t & 1;
    if (i >= N) return;
    float4 acc = g_xs[i * 2 + hf];                  // self-loop term
    int beg = g_rowstart[i], end = g_rowstart[i + 1];
    int j = beg;
    for (; j + 3 < end; j += 4) {
        int s0 = g_csr[j], s1 = g_csr[j + 1], s2 = g_csr[j + 2], s3 = g_csr[j + 3];
        float4 v0 = g_xs[s0 * 2 + hf];
        float4 v1 = g_xs[s1 * 2 + hf];
        float4 v2 = g_xs[s2 * 2 + hf];
        float4 v3 = g_xs[s3 * 2 + hf];
        f4add(acc, v0); f4add(acc, v1); f4add(acc, v2); f4add(acc, v3);
    }
    for (; j < end; j++) f4add(acc, g_xs[g_csr[j] * 2 + hf]);

    float4 other;
    other.x = __shfl_xor_sync(0xffffffffu, acc.x, 1);
    other.y = __shfl_xor_sync(0xffffffffu, acc.y, 1);
    other.z = __shfl_xor_sync(0xffffffffu, acc.z, 1);
    other.w = __shfl_xor_sync(0xffffffffu, acc.w, 1);
    float a[6];
    if (hf == 0) { a[0]=acc.x; a[1]=acc.y; a[2]=acc.z; a[3]=acc.w; a[4]=other.x; a[5]=other.y; }
    else         { a[0]=other.x; a[1]=other.y; a[2]=other.z; a[3]=other.w; a[4]=acc.x; a[5]=acc.y; }

    const float4* W14 = (const float4*)W1;          // [6][16] float4
    const float4* b14 = (const float4*)b1;          // [16] float4
    float4 out[8];
#pragma unroll
    for (int c = 0; c < 8; c++) out[c] = f4zero();
#pragma unroll
    for (int k = 0; k < 6; k++) {
#pragma unroll
        for (int c = 0; c < 8; c++) {
            float4 w = __ldg(&W14[k * 16 + hf * 8 + c]);
            f4fma(out[c], a[k], w);
        }
    }
    float di = g_dinv[i];
    __half2 hh[16];
#pragma unroll
    for (int c = 0; c < 8; c++) {
        float4 b = __ldg(&b14[hf * 8 + c]);
        float hx = fmaxf(fmaf(di, out[c].x, b.x), 0.f) * di;
        float hy = fmaxf(fmaf(di, out[c].y, b.y), 0.f) * di;
        float hz = fmaxf(fmaf(di, out[c].z, b.z), 0.f) * di;
        float hw = fmaxf(fmaf(di, out[c].w, b.w), 0.f) * di;
        hh[2 * c + 0] = __floats2half2_rn(hx, hy);
        hh[2 * c + 1] = __floats2half2_rn(hz, hw);
    }
    uint4* dst = (uint4*)(g_hs + (size_t)i * 64 + hf * 32);
    const uint4* s4 = (const uint4*)hh;
#pragma unroll
    for (int q = 0; q < 4; q++) dst[q] = s4[q];
}

// ---------------- layer 2 fused: gather + W2 (f32x2) + relu + segmented pool ---
// 8 lanes per node; lane c owns outputs [8c, 8c+8).
__global__ void __launch_bounds__(256) k_layer2(int N, const float* __restrict__ b2,
                                                const int* __restrict__ batch) {
    const unsigned F = 0xffffffffu;
    int t = blockIdx.x * blockDim.x + threadIdx.x;
    int i = t >> 3;
    int c = t & 7;
    int lane = threadIdx.x & 31;
    int q = (lane >> 3);                            // node-group within warp (0..3)
    bool valid = i < N;

    const uint4* hs4 = (const uint4*)g_hs;
    float acc[8];
#pragma unroll
    for (int r = 0; r < 8; r++) acc[r] = 0.f;
    if (valid) {
        uint4 v = hs4[(size_t)i * 8 + c];           // self
        addcvt(acc, v);
        int beg = g_rowstart[i], end = g_rowstart[i + 1];
        int j = beg;
        for (; j + 3 < end; j += 4) {
            int s0 = g_csr[j], s1 = g_csr[j + 1], s2 = g_csr[j + 2], s3 = g_csr[j + 3];
            uint4 v0 = hs4[(size_t)s0 * 8 + c];
            uint4 v1 = hs4[(size_t)s1 * 8 + c];
            uint4 v2 = hs4[(size_t)s2 * 8 + c];
            uint4 v3 = hs4[(size_t)s3 * 8 + c];
            addcvt(acc, v0); addcvt(acc, v1); addcvt(acc, v2); addcvt(acc, v3);
        }
        for (; j < end; j++) addcvt(acc, hs4[(size_t)g_csr[j] * 8 + c]);
    }

    // distributed matvec: t[k] broadcast from owning lane, f32x2 FMAs.
    ull out2[4] = {0ull, 0ull, 0ull, 0ull};
#pragma unroll
    for (int q8 = 0; q8 < 8; q8++) {
#pragma unroll
        for (int jj = 0; jj < 8; jj++) {
            float tv = __shfl_sync(F, acc[jj], q8, 8);
            int k = q8 * 8 + jj;
            ulonglong2 wA = g_W2p[k * 16 + c * 2];
            ulonglong2 wB = g_W2p[k * 16 + c * 2 + 1];
            ull tp = pk2(tv, tv);
            out2[0] = f2fma(tp, wA.x, out2[0]);
            out2[1] = f2fma(tp, wA.y, out2[1]);
            out2[2] = f2fma(tp, wB.x, out2[2]);
            out2[3] = f2fma(tp, wB.y, out2[3]);
        }
    }

    float di = valid ? g_dinv[i] : 0.f;
    int g = valid ? batch[i] : -1;
    float hv[8];
#pragma unroll
    for (int m = 0; m < 4; m++) {
        float2 f = upk2(out2[m]);
        hv[2 * m]     = fmaxf(fmaf(di, f.x, __ldg(&b2[c * 8 + 2 * m])), 0.f);
        hv[2 * m + 1] = fmaxf(fmaf(di, f.y, __ldg(&b2[c * 8 + 2 * m + 1])), 0.f);
    }
    if (!valid) {
#pragma unroll
        for (int r = 0; r < 8; r++) hv[r] = 0.f;
    }

    // segmented pooling across the warp's 4 node-groups (batch is sorted)
    int gprev = __shfl_up_sync(F, g, 8);
    bool head = valid && ((q == 0) || (g != gprev));
    float sum[8];
#pragma unroll
    for (int r = 0; r < 8; r++) sum[r] = hv[r];
    float cntrun = 1.f;
#pragma unroll
    for (int d = 1; d < 4; d++) {
        int srcLane = (lane + d * 8) & 31;
        int gd = __shfl_sync(F, g, srcLane);
        bool take = head && (q + d < 4) && (gd == g);
#pragma unroll
        for (int r = 0; r < 8; r++) {
            float v = __shfl_sync(F, hv[r], srcLane);
            if (take) sum[r] += v;
        }
        if (take) cntrun += 1.f;
    }
    if (head) {
        float* pp = (float*)g_pooled + (size_t)g * 64 + c * 8;
#pragma unroll
        for (int r = 0; r < 8; r++) atomicAdd(pp + r, sum[r]);
        if (c == 0) atomicAdd(&g_cnt[g], cntrun);
    }
}

// ---------------- final MLP ----------------------------------------------------
__global__ void k_mlp(int G,
                      const float* __restrict__ embL, const float* __restrict__ embA,
                      const float* __restrict__ embB, const float* __restrict__ embAr,
                      const int* __restrict__ lig, const int* __restrict__ add,
                      const int* __restrict__ base, const int* __restrict__ aryl,
                      const float* __restrict__ lin1W, const float* __restrict__ lin1b,
                      const float* __restrict__ lin2W, const float* __restrict__ lin2b,
                      float* __restrict__ out) {
    __shared__ float cat[2][128];
    __shared__ float red[2][2];
    int local = threadIdx.x >> 6;
    int o = threadIdx.x & 63;
    int g = blockIdx.x * 2 + local;
    if (g < G) {
        float cnt = fmaxf(g_cnt[g], 1.f);
        const float* pooled = (const float*)&g_pooled[g * 16];
        cat[local][o] = pooled[o] / cnt;
        float ev;
        if (o < 16)       ev = embL[lig[g] * 16 + o];
        else if (o < 32)  ev = embA[add[g] * 16 + (o - 16)];
        else if (o < 48)  ev = embB[base[g] * 16 + (o - 32)];
        else              ev = embAr[aryl[g] * 16 + (o - 48)];
        cat[local][64 + o] = ev;
    }
    __syncthreads();
    float term = 0.f;
    if (g < G) {
        float acc = lin1b[o];
#pragma unroll 8
        for (int k = 0; k < 128; k++)
            acc = fmaf(cat[local][k], __ldg(&lin1W[k * 64 + o]), acc);
        acc = fmaxf(acc, 0.f);
        term = acc * __ldg(&lin2W[o]);
#pragma unroll
        for (int off = 16; off > 0; off >>= 1)
            term += __shfl_down_sync(0xffffffffu, term, off);
        if ((o & 31) == 0) red[local][o >> 5] = term;
    }
    __syncthreads();
    if (g < G && o == 0) out[g] = red[local][0] + red[local][1] + lin2b[0];
}

// ---------------- launch ------------------------------------------------------
extern "C" void kernel_launch(void* const* d_in, const int* in_sizes, int n_in,
                              void* d_out, int out_size) {
    const float* x      = (const float*)d_in[0];
    const int*   ei     = (const int*)d_in[1];
    const int*   batch  = (const int*)d_in[2];
    const int*   lig    = (const int*)d_in[3];
    const int*   addi   = (const int*)d_in[4];
    const int*   basei  = (const int*)d_in[5];
    const int*   aryl   = (const int*)d_in[6];
    const float* embL   = (const float*)d_in[7];
    const float* embA   = (const float*)d_in[8];
    const float* embB   = (const float*)d_in[9];
    const float* embAr  = (const float*)d_in[10];
    const float* W1     = (const float*)d_in[11];
    const float* b1     = (const float*)d_in[12];
    const float* W2     = (const float*)d_in[13];
    const float* b2     = (const float*)d_in[14];
    const float* lin1W  = (const float*)d_in[15];
    const float* lin1b  = (const float*)d_in[16];
    const float* lin2W  = (const float*)d_in[17];
    const float* lin2b  = (const float*)d_in[18];

    int N = in_sizes[0] / 6;
    int E = in_sizes[1] / 2;
    int G = in_sizes[3];
    const int* src = ei;
    const int* dst = ei + E;
    int nb = (N + SCAN_B - 1) / SCAN_B;
    int e4 = (E + 3) / 4;

    int zmax = N > G * 16 ? N : G * 16;
    k_zero<<<(zmax + 255) / 256, 256>>>(N, G, W2);
    k_deg<<<(e4 + 255) / 256, 256>>>(dst, E);
    k_scanfuse<<<nb, SCAN_B>>>(N, E, x);
    k_fill<<<(e4 + 255) / 256, 256>>>(src, dst, E);
    k_layer1<<<((long)N * 2 + 255) / 256, 256>>>(N, W1, b1);
    k_layer2<<<((long)N * 8 + 255) / 256, 256>>>(N, b2, batch);
    k_mlp<<<(G + 1) / 2, 128>>>(G, embL, embA, embB, embAr,
                                lig, addi, basei, aryl,
                                lin1W, lin1b, lin2W, lin2b, (float*)d_out);
}